// round 1
// baseline (speedup 1.0000x reference)
#include <cuda_runtime.h>
#include <cuda_bf16.h>

#define D 128

__global__ __launch_bounds__(256) void arccos_hess_kernel(
    const float* __restrict__ z1,
    const float* __restrict__ z2,
    float* __restrict__ out,
    int B)
{
    int b = blockIdx.x;
    __shared__ float a[D];   // z1 unit vector
    __shared__ float v[D];   // z2 unit vector
    __shared__ float r11[8], r22[8], r12[8];
    __shared__ float s_c, s_i11, s_i12, s_i22, s_rn1, s_rn2;

    int tid = threadIdx.x;

    float x1 = 0.f, x2 = 0.f;
    if (tid < D) {
        x1 = z1[(size_t)b * D + tid];
        x2 = z2[(size_t)b * D + tid];
    }

    // Block reduction of s11 = sum z1*z1, s22 = sum z2*z2, s12 = sum z1*z2
    float p11 = x1 * x1, p22 = x2 * x2, p12 = x1 * x2;
    #pragma unroll
    for (int o = 16; o; o >>= 1) {
        p11 += __shfl_down_sync(0xffffffffu, p11, o);
        p22 += __shfl_down_sync(0xffffffffu, p22, o);
        p12 += __shfl_down_sync(0xffffffffu, p12, o);
    }
    int wid = tid >> 5;
    if ((tid & 31) == 0) { r11[wid] = p11; r22[wid] = p22; r12[wid] = p12; }
    __syncthreads();

    if (tid == 0) {
        float s11 = 0.f, s22 = 0.f, s12 = 0.f;
        #pragma unroll
        for (int w = 0; w < 8; w++) { s11 += r11[w]; s22 += r22[w]; s12 += r12[w]; }
        float rn1 = rsqrtf(s11);
        float rn2 = rsqrtf(s22);
        s_rn1 = rn1;
        s_rn2 = rn2;
        s_c   = s12 * rn1 * rn2;
        s_i11 = rn1 * rn1;
        s_i22 = rn2 * rn2;
        s_i12 = rn1 * rn2;
    }
    __syncthreads();

    if (tid < D) {
        a[tid] = x1 * s_rn1;
        v[tid] = x2 * s_rn2;
    }
    __syncthreads();

    float c   = s_c;
    float i11 = s_i11, i12 = s_i12, i22 = s_i22;
    float c3  = 3.0f * c;

    size_t bdd     = (size_t)b * D * D;
    size_t mstride = (size_t)B * D * D;

    // 3 matrices * 128 rows * 32 float4-quads = 12288 slots, stride 256.
    // x = s >> 12 is uniform across the block each iteration (4096 % 256 == 0).
    for (int s = tid; s < 3 * D * (D / 4); s += 256) {
        int x   = s >> 12;
        int rem = s & 4095;
        int i   = rem >> 5;
        int j   = (rem & 31) << 2;

        float ai = a[i];
        float vi = v[i];
        float4 aj = *reinterpret_cast<const float4*>(&a[j]);
        float4 vj = *reinterpret_cast<const float4*>(&v[j]);
        const float* paj = &aj.x;
        const float* pvj = &vj.x;

        float4 r;
        float* pr = &r.x;

        if (x == 0) {
            // H11 = (c*I + a v^T + v a^T - 3c * a a^T) * i11
            #pragma unroll
            for (int k = 0; k < 4; k++) {
                float e = (i == j + k) ? c : 0.f;
                pr[k] = (e + ai * pvj[k] + vi * paj[k] - c3 * ai * paj[k]) * i11;
            }
        } else if (x == 1) {
            // H12 = (-I + a a^T + v v^T - c * v a^T) * i12
            #pragma unroll
            for (int k = 0; k < 4; k++) {
                float e = (i == j + k) ? -1.f : 0.f;
                pr[k] = (e + ai * paj[k] + vi * pvj[k] - c * vi * paj[k]) * i12;
            }
        } else {
            // H22 = (c*I + a v^T + v a^T - 3c * v v^T) * i22
            #pragma unroll
            for (int k = 0; k < 4; k++) {
                float e = (i == j + k) ? c : 0.f;
                pr[k] = (e + ai * pvj[k] + vi * paj[k] - c3 * vi * pvj[k]) * i22;
            }
        }

        *reinterpret_cast<float4*>(&out[(size_t)x * mstride + bdd + (size_t)i * D + j]) = r;
    }
}

extern "C" void kernel_launch(void* const* d_in, const int* in_sizes, int n_in,
                              void* d_out, int out_size) {
    const float* z1 = (const float*)d_in[0];
    const float* z2 = (const float*)d_in[1];
    float* out = (float*)d_out;
    int B = in_sizes[0] / D;   // 4096
    arccos_hess_kernel<<<B, 256>>>(z1, z2, out, B);
}

// round 3
// speedup vs baseline: 1.4035x; 1.4035x over previous
#include <cuda_runtime.h>
#include <cuda_bf16.h>

#define D 128

__global__ __launch_bounds__(256) void arccos_hess_kernel(
    const float* __restrict__ z1,
    const float* __restrict__ z2,
    float* __restrict__ out,
    int B)
{
    int b = blockIdx.x;
    __shared__ float a[D];   // z1 unit vector
    __shared__ float v[D];   // z2 unit vector
    __shared__ float r11[8], r22[8], r12[8];
    __shared__ float s_c, s_i11, s_i12, s_i22, s_rn1, s_rn2;

    int tid = threadIdx.x;

    float x1 = 0.f, x2 = 0.f;
    if (tid < D) {
        x1 = z1[(size_t)b * D + tid];
        x2 = z2[(size_t)b * D + tid];
    }

    // Block reduction of s11, s22, s12
    float p11 = x1 * x1, p22 = x2 * x2, p12 = x1 * x2;
    #pragma unroll
    for (int o = 16; o; o >>= 1) {
        p11 += __shfl_down_sync(0xffffffffu, p11, o);
        p22 += __shfl_down_sync(0xffffffffu, p22, o);
        p12 += __shfl_down_sync(0xffffffffu, p12, o);
    }
    int wid = tid >> 5;
    if ((tid & 31) == 0) { r11[wid] = p11; r22[wid] = p22; r12[wid] = p12; }
    __syncthreads();

    if (tid == 0) {
        float s11 = 0.f, s22 = 0.f, s12 = 0.f;
        #pragma unroll
        for (int w = 0; w < 8; w++) { s11 += r11[w]; s22 += r22[w]; s12 += r12[w]; }
        float rn1 = rsqrtf(s11);
        float rn2 = rsqrtf(s22);
        s_rn1 = rn1;
        s_rn2 = rn2;
        s_c   = s12 * rn1 * rn2;
        s_i11 = rn1 * rn1;
        s_i22 = rn2 * rn2;
        s_i12 = rn1 * rn2;
    }
    __syncthreads();

    if (tid < D) {
        a[tid] = x1 * s_rn1;
        v[tid] = x2 * s_rn2;
    }
    __syncthreads();

    float c   = s_c;
    float i11 = s_i11, i12 = s_i12, i22 = s_i22;
    float c3  = 3.0f * c;

    size_t bdd     = (size_t)b * D * D;
    size_t mstride = (size_t)B * D * D;
    float* o11 = out + bdd;
    float* o12 = out + mstride + bdd;
    float* o22 = out + 2 * mstride + bdd;

    // 128 rows * 32 float4-quads = 4096 slots, stride 256 -> 16 iterations.
    // Each (i,j) quad visited ONCE; all three matrices written from shared
    // register products. Warp lanes cover one full row quad-contiguously.
    for (int s = tid; s < D * (D / 4); s += 256) {
        int i = s >> 5;
        int j = (s & 31) << 2;

        float ai = a[i];
        float vi = v[i];
        float4 aj = *reinterpret_cast<const float4*>(&a[j]);
        float4 vj = *reinterpret_cast<const float4*>(&v[j]);
        const float* paj = &aj.x;
        const float* pvj = &vj.x;

        float4 h11, h12, h22;
        float* p11o = &h11.x;
        float* p12o = &h12.x;
        float* p22o = &h22.x;

        int d = i - j;   // diagonal hits when d == k (0..3)

        #pragma unroll
        for (int k = 0; k < 4; k++) {
            float ajk = paj[k], vjk = pvj[k];
            float aa = ai * ajk;
            float vv = vi * vjk;
            float av = ai * vjk;
            float va = vi * ajk;
            float T  = av + va;
            bool  dg = (d == k);
            float ec = dg ? c : 0.f;
            float e1 = dg ? -1.f : 0.f;
            p11o[k] = (ec + T - c3 * aa) * i11;
            p12o[k] = (e1 + aa + vv - c * va) * i12;
            p22o[k] = (ec + T - c3 * vv) * i22;
        }

        size_t off = (size_t)i * D + j;
        __stcs(reinterpret_cast<float4*>(o11 + off), h11);
        __stcs(reinterpret_cast<float4*>(o12 + off), h12);
        __stcs(reinterpret_cast<float4*>(o22 + off), h22);
    }
}

extern "C" void kernel_launch(void* const* d_in, const int* in_sizes, int n_in,
                              void* d_out, int out_size) {
    const float* z1 = (const float*)d_in[0];
    const float* z2 = (const float*)d_in[1];
    float* out = (float*)d_out;
    int B = in_sizes[0] / D;   // 4096
    arccos_hess_kernel<<<B, 256>>>(z1, z2, out, B);
}